// round 14
// baseline (speedup 1.0000x reference)
#include <cuda_runtime.h>
#include <cuda_fp16.h>
#include <cstdint>
#include <cstddef>

#define D 128
#define MAXN 100000
#define MAXE 500000
#define MAXR 237
#define SCB  512
#define NBLK ((MAXN + SCB - 1) / SCB)

// ---- scratch (device globals) ----
__device__ float  g_Mcat[D * 256];           // fused W_ent@[W2a|W2b], [128][256]
__device__ float  g_bias[256];
__device__ float  g_pc[MAXR * D];
__device__ float  g_qc[MAXR];
__device__ float  g_pa[(size_t)MAXN * D];    // fp32
__device__ __half g_pbh[(size_t)MAXN * D];   // fp16 (gathered side)
__device__ float  g_qa[MAXN];
__device__ float  g_qb[MAXN];
__device__ float2 g_epk[MAXE];               // (b_e, dst|rel<<17)
__device__ int    g_cnt[MAXN];
__device__ int    g_rowptr[MAXN + 1];
__device__ int    g_cursor[MAXN];
__device__ int    g_bsum[NBLK];
__device__ int    g_boff[NBLK];

// ---- f32x2 packed-FMA helpers ----
__device__ __forceinline__ unsigned long long pk2(float lo, float hi) {
    unsigned long long r;
    asm("mov.b64 %0, {%1, %2};" : "=l"(r) : "f"(lo), "f"(hi));
    return r;
}
__device__ __forceinline__ void upk2(unsigned long long v, float& lo, float& hi) {
    asm("mov.b64 {%0, %1}, %2;" : "=f"(lo), "=f"(hi) : "l"(v));
}
__device__ __forceinline__ unsigned long long fma2(unsigned long long a,
                                                   unsigned long long b,
                                                   unsigned long long c) {
    unsigned long long d;
    asm("fma.rn.f32x2 %0, %1, %2, %3;" : "=l"(d) : "l"(a), "l"(b), "l"(c));
    return d;
}

// ---- kernel 1: weight fusion, per-relation term + qc, bias; zero histogram ----
__global__ void prep_kernel(const float* __restrict__ W_ent,
                            const float* __restrict__ b_ent,
                            const float* __restrict__ W_rel,
                            const float* __restrict__ b_rel,
                            const float* __restrict__ W_ent2,
                            const float* __restrict__ b_ent2,
                            const float* __restrict__ rel_embed,
                            const float* __restrict__ a_w,
                            int n_rels, int n_nodes) {
    int b = blockIdx.x, t = threadIdx.x;
    if (b < D) {
        __shared__ float wrow[D];
        wrow[t] = W_ent[b * D + t];
        __syncthreads();
        float s0 = 0.f, s1 = 0.f;
#pragma unroll 4
        for (int k = 0; k < D; k++) {
            float w = wrow[k];
            s0 += w * W_ent2[k * D + t];
            s1 += w * W_ent2[(D + k) * D + t];
        }
        g_Mcat[b * 256 + t]     = s0;
        g_Mcat[b * 256 + D + t] = s1;
    } else if (b < D + n_rels) {
        int r = b - D;
        __shared__ float rp[D];
        __shared__ float red[D];
        float s = b_rel[t];
#pragma unroll 4
        for (int i = 0; i < D; i++) s += rel_embed[r * D + i] * W_rel[i * D + t];
        rp[t] = s;
        __syncthreads();
        float o = b_ent2[t];
#pragma unroll 4
        for (int k = 0; k < D; k++) o += rp[k] * W_ent2[(2 * D + k) * D + t];
        g_pc[r * D + t] = o;
        red[t] = o * a_w[t];
        __syncthreads();
        for (int off = 64; off > 0; off >>= 1) {
            if (t < off) red[t] += red[t + off];
            __syncthreads();
        }
        if (t == 0) g_qc[r] = red[0];
    } else {
        float s0 = 0.f, s1 = 0.f;
        for (int k = 0; k < D; k++) {
            float bv = b_ent[k];
            s0 += bv * W_ent2[k * D + t];
            s1 += bv * W_ent2[(D + k) * D + t];
        }
        g_bias[t]     = s0;
        g_bias[D + t] = s1;
    }
    for (int i = b * blockDim.x + t; i < n_nodes; i += gridDim.x * blockDim.x)
        g_cnt[i] = 0;
}

// ---- kernel 2: out-degree histogram ----
__global__ void hist_kernel(const int* __restrict__ trip, int E) {
    for (int e = blockIdx.x * blockDim.x + threadIdx.x; e < E;
         e += gridDim.x * blockDim.x)
        atomicAdd(&g_cnt[trip[e * 3]], 1);
}

// ---- kernels 3a/3b/3c: multi-block exclusive scan ----
__global__ void scan1_kernel(int N) {
    __shared__ int sm[SCB];
    int t = threadIdx.x;
    int i = blockIdx.x * SCB + t;
    sm[t] = (i < N) ? g_cnt[i] : 0;
    __syncthreads();
    for (int off = SCB / 2; off > 0; off >>= 1) {
        if (t < off) sm[t] += sm[t + off];
        __syncthreads();
    }
    if (t == 0) g_bsum[blockIdx.x] = sm[0];
}
__global__ void scan2_kernel(int nblk, int N) {
    __shared__ int sm[256];
    int t = threadIdx.x;
    int v = (t < nblk) ? g_bsum[t] : 0;
    sm[t] = v;
    __syncthreads();
    for (int off = 1; off < 256; off <<= 1) {
        int u = (t >= off) ? sm[t - off] : 0;
        __syncthreads();
        sm[t] += u;
        __syncthreads();
    }
    if (t < nblk) g_boff[t] = sm[t] - v;
    if (t == 255) g_rowptr[N] = sm[255];
}
__global__ void scan3_kernel(int N) {
    __shared__ int sm[SCB];
    int t = threadIdx.x;
    int i = blockIdx.x * SCB + t;
    int v = (i < N) ? g_cnt[i] : 0;
    sm[t] = v;
    __syncthreads();
    for (int off = 1; off < SCB; off <<= 1) {
        int u = (t >= off) ? sm[t - off] : 0;
        __syncthreads();
        sm[t] += u;
        __syncthreads();
    }
    if (i < N) {
        int val = g_boff[blockIdx.x] + sm[t] - v;
        g_rowptr[i] = val;
        g_cursor[i] = val;
    }
}

// ---- kernel 4 (slot 3): FFMA2 GEMM, 128x128 per CTA, software-pipelined ----
__global__ __launch_bounds__(256, 2) void gemm_kernel(const float* __restrict__ ent,
                                                      const float* __restrict__ a_w,
                                                      int N) {
    extern __shared__ float smem[];
    float*  As = smem;                       // 64 k x 128 rows = 32 KB (per phase)
    float2* Bd = (float2*)(smem + 64 * D);   // 64 k x 128 dup-pairs = 64 KB
    const int tid = threadIdx.x;
    const int rb = blockIdx.x * 128;
    const int y = blockIdx.y;
    const int tc = tid & 31, tr = tid >> 5;
    const int tr4 = tr * 4;

    unsigned long long acc[8][4];
    {
        const float* bi = g_bias + y * D + tc * 4;
#pragma unroll
        for (int c = 0; c < 4; c++) {
            unsigned long long p = pk2(bi[c], bi[c]);
#pragma unroll
            for (int j = 0; j < 8; j++) acc[j][c] = p;
        }
    }

    const ulonglong2* As2 = (const ulonglong2*)As;
    const ulonglong2* Bd2 = (const ulonglong2*)Bd;
    const float4* M4 = (const float4*)g_Mcat;
    const float4* E4 = (const float4*)ent;

#pragma unroll 1
    for (int ph = 0; ph < 2; ph++) {
        __syncthreads();
        // fill As: rows 0..127 x local k 0..63, row-chunk XOR swizzle
#pragma unroll
        for (int j = 0; j < 8; j++) {
            int f = j * 256 + tid;
            int r = f >> 4, kq4 = f & 15;
            int row = rb + r;
            if (row >= N) row = N - 1;
            float4 g = E4[(size_t)row * 32 + ph * 16 + kq4];
            int rs = r ^ ((kq4 & 7) << 2);
            float* dp = As + (kq4 * 4) * 128 + rs;
            dp[0] = g.x; dp[128] = g.y; dp[256] = g.z; dp[384] = g.w;
        }
        // fill Bd: interleaved duplicated pairs, dense 16B lane stride
#pragma unroll
        for (int j = 0; j < 8; j++) {
            int f = j * 256 + tid;
            int kk = f >> 5, c4 = f & 31;
            float4 v = M4[(ph * 64 + kk) * 64 + y * 32 + c4];
            float4* d0 = (float4*)((char*)Bd + kk * 1024 + c4 * 16);
            float4* d1 = (float4*)((char*)Bd + kk * 1024 + 512 + c4 * 16);
            *d0 = make_float4(v.x, v.x, v.y, v.y);
            *d1 = make_float4(v.z, v.z, v.w, v.w);
        }
        __syncthreads();

        // software-pipelined k-loop: load k+1 while FMA-ing k
        ulonglong2 pa0[2], pa1[2], pa2[2], pa3[2], pb01[2], pb23[2];
        {
            int x0 = 0;
            pa0[0] = As2[(tr4 + 0) ^ x0];
            pa1[0] = As2[(tr4 + 1) ^ x0];
            pa2[0] = As2[(tr4 + 2) ^ x0];
            pa3[0] = As2[(tr4 + 3) ^ x0];
            pb01[0] = Bd2[tc];
            pb23[0] = Bd2[32 + tc];
        }
#pragma unroll 4
        for (int kk = 0; kk < 64; kk++) {
            const int cur = kk & 1, nxt = cur ^ 1;
            {
                int kn = (kk + 1) & 63;          // wraps at 63 -> discarded
                int xn = (kn >> 2) & 7;
                pa0[nxt] = As2[kn * 32 + ((tr4 + 0) ^ xn)];
                pa1[nxt] = As2[kn * 32 + ((tr4 + 1) ^ xn)];
                pa2[nxt] = As2[kn * 32 + ((tr4 + 2) ^ xn)];
                pa3[nxt] = As2[kn * 32 + ((tr4 + 3) ^ xn)];
                pb01[nxt] = Bd2[kn * 64 + tc];
                pb23[nxt] = Bd2[kn * 64 + 32 + tc];
            }
            ulonglong2 a0 = pa0[cur], a1 = pa1[cur], a2 = pa2[cur], a3 = pa3[cur];
            ulonglong2 b01 = pb01[cur], b23 = pb23[cur];
            acc[0][0] = fma2(a0.x, b01.x, acc[0][0]);
            acc[0][1] = fma2(a0.x, b01.y, acc[0][1]);
            acc[0][2] = fma2(a0.x, b23.x, acc[0][2]);
            acc[0][3] = fma2(a0.x, b23.y, acc[0][3]);
            acc[1][0] = fma2(a0.y, b01.x, acc[1][0]);
            acc[1][1] = fma2(a0.y, b01.y, acc[1][1]);
            acc[1][2] = fma2(a0.y, b23.x, acc[1][2]);
            acc[1][3] = fma2(a0.y, b23.y, acc[1][3]);
            acc[2][0] = fma2(a1.x, b01.x, acc[2][0]);
            acc[2][1] = fma2(a1.x, b01.y, acc[2][1]);
            acc[2][2] = fma2(a1.x, b23.x, acc[2][2]);
            acc[2][3] = fma2(a1.x, b23.y, acc[2][3]);
            acc[3][0] = fma2(a1.y, b01.x, acc[3][0]);
            acc[3][1] = fma2(a1.y, b01.y, acc[3][1]);
            acc[3][2] = fma2(a1.y, b23.x, acc[3][2]);
            acc[3][3] = fma2(a1.y, b23.y, acc[3][3]);
            acc[4][0] = fma2(a2.x, b01.x, acc[4][0]);
            acc[4][1] = fma2(a2.x, b01.y, acc[4][1]);
            acc[4][2] = fma2(a2.x, b23.x, acc[4][2]);
            acc[4][3] = fma2(a2.x, b23.y, acc[4][3]);
            acc[5][0] = fma2(a2.y, b01.x, acc[5][0]);
            acc[5][1] = fma2(a2.y, b01.y, acc[5][1]);
            acc[5][2] = fma2(a2.y, b23.x, acc[5][2]);
            acc[5][3] = fma2(a2.y, b23.y, acc[5][3]);
            acc[6][0] = fma2(a3.x, b01.x, acc[6][0]);
            acc[6][1] = fma2(a3.x, b01.y, acc[6][1]);
            acc[6][2] = fma2(a3.x, b23.x, acc[6][2]);
            acc[6][3] = fma2(a3.x, b23.y, acc[6][3]);
            acc[7][0] = fma2(a3.y, b01.x, acc[7][0]);
            acc[7][1] = fma2(a3.y, b01.y, acc[7][1]);
            acc[7][2] = fma2(a3.y, b23.x, acc[7][2]);
            acc[7][3] = fma2(a3.y, b23.y, acc[7][3]);
        }
    }

    // epilogue: 16 rows x 4 cols per thread; store + per-row a_w dot
    const float4 aw4 = ((const float4*)a_w)[tc];
    float qv[16];
#pragma unroll
    for (int p = 0; p < 8; p++) {
        float4 lo4, hi4;
        upk2(acc[p][0], lo4.x, hi4.x);
        upk2(acc[p][1], lo4.y, hi4.y);
        upk2(acc[p][2], lo4.z, hi4.z);
        upk2(acc[p][3], lo4.w, hi4.w);
        qv[p * 2]     = lo4.x * aw4.x + lo4.y * aw4.y + lo4.z * aw4.z + lo4.w * aw4.w;
        qv[p * 2 + 1] = hi4.x * aw4.x + hi4.y * aw4.y + hi4.z * aw4.z + hi4.w * aw4.w;
        int r0 = rb + tr * 16 + p * 2;
        if (y == 0) {
            float4* out4 = (float4*)g_pa;
            if (r0 < N)     out4[(size_t)r0 * 32 + tc] = lo4;
            if (r0 + 1 < N) out4[(size_t)(r0 + 1) * 32 + tc] = hi4;
        } else {
            uint2* outh = (uint2*)g_pbh;
            __half2 a0h = __floats2half2_rn(lo4.x, lo4.y);
            __half2 a1h = __floats2half2_rn(lo4.z, lo4.w);
            __half2 b0h = __floats2half2_rn(hi4.x, hi4.y);
            __half2 b1h = __floats2half2_rn(hi4.z, hi4.w);
            uint2 ulo, uhi;
            ulo.x = *(unsigned int*)&a0h; ulo.y = *(unsigned int*)&a1h;
            uhi.x = *(unsigned int*)&b0h; uhi.y = *(unsigned int*)&b1h;
            if (r0 < N)     outh[(size_t)r0 * 32 + tc] = ulo;
            if (r0 + 1 < N) outh[(size_t)(r0 + 1) * 32 + tc] = uhi;
        }
    }
#pragma unroll
    for (int off = 16; off > 0; off >>= 1) {
#pragma unroll
        for (int i = 0; i < 16; i++)
            qv[i] += __shfl_xor_sync(0xffffffffu, qv[i], off);
    }
    if (tc == 0) {
        float* q = (y == 0) ? g_qa : g_qb;
#pragma unroll
        for (int i = 0; i < 16; i++) {
            int r = rb + tr * 16 + i;
            if (r < N) q[r] = qv[i];
        }
    }
}

// ---- kernel 5: scatter edges into CSR + edge weight (packed record) ----
__global__ void scatter_b_kernel(const int* __restrict__ trip,
                                 const float* __restrict__ abp, int E) {
    float ab = abp[0];
    for (int e = blockIdx.x * blockDim.x + threadIdx.x; e < E;
         e += gridDim.x * blockDim.x) {
        int src = trip[e * 3];
        int dst = trip[e * 3 + 1];
        int rel = trip[e * 3 + 2];
        int p = atomicAdd(&g_cursor[src], 1);
        float s = g_qa[src] + g_qb[dst] + g_qc[rel] + ab;
        s = s > 0.f ? s : 0.01f * s;   // leaky_relu(0.01)
        float2 rec;
        rec.x = __expf(s);
        rec.y = __int_as_float(dst | (rel << 17));
        g_epk[p] = rec;
    }
}

// ---- kernel 6: warp-per-node aggregation (unrolled x2) ----
__global__ void agg_kernel(float* __restrict__ h, int N) {
    int gw = (blockIdx.x * blockDim.x + threadIdx.x) >> 5;
    int lane = threadIdx.x & 31;
    if (gw >= N) return;
    int beg = g_rowptr[gw], end = g_rowptr[gw + 1];
    if (beg == end) {
        float4 z = {0.f, 0.f, 0.f, 0.f};
        ((float4*)h)[(size_t)gw * 32 + lane] = z;
        return;
    }
    const uint2* pbh2 = (const uint2*)g_pbh;
    const float4* pc4 = (const float4*)g_pc;
    float4 acc = {0.f, 0.f, 0.f, 0.f};
    float bsum = 0.f;
    int e = beg;
    for (; e + 1 < end; e += 2) {
        float2 r0 = g_epk[e];
        float2 r1 = g_epk[e + 1];
        int p0 = __float_as_int(r0.y), p1 = __float_as_int(r1.y);
        uint2 u0 = pbh2[(size_t)(p0 & 0x1FFFF) * 32 + lane];
        uint2 u1 = pbh2[(size_t)(p1 & 0x1FFFF) * 32 + lane];
        float4 c0 = pc4[(p0 >> 17) * 32 + lane];
        float4 c1 = pc4[(p1 >> 17) * 32 + lane];
        float b0 = r0.x, b1 = r1.x;
        float2 f00 = __half22float2(*(__half2*)&u0.x);
        float2 f01 = __half22float2(*(__half2*)&u0.y);
        float2 f10 = __half22float2(*(__half2*)&u1.x);
        float2 f11 = __half22float2(*(__half2*)&u1.y);
        bsum += b0 + b1;
        acc.x += b0 * (f00.x + c0.x) + b1 * (f10.x + c1.x);
        acc.y += b0 * (f00.y + c0.y) + b1 * (f10.y + c1.y);
        acc.z += b0 * (f01.x + c0.z) + b1 * (f11.x + c1.z);
        acc.w += b0 * (f01.y + c0.w) + b1 * (f11.y + c1.w);
    }
    if (e < end) {
        float2 r0 = g_epk[e];
        int p0 = __float_as_int(r0.y);
        uint2 u0 = pbh2[(size_t)(p0 & 0x1FFFF) * 32 + lane];
        float4 c0 = pc4[(p0 >> 17) * 32 + lane];
        float b0 = r0.x;
        float2 f00 = __half22float2(*(__half2*)&u0.x);
        float2 f01 = __half22float2(*(__half2*)&u0.y);
        bsum += b0;
        acc.x += b0 * (f00.x + c0.x);
        acc.y += b0 * (f00.y + c0.y);
        acc.z += b0 * (f01.x + c0.z);
        acc.w += b0 * (f01.y + c0.w);
    }
    float4 pa = ((const float4*)g_pa)[(size_t)gw * 32 + lane];
    float inv = 1.f / bsum;
    float4 o;
    o.x = pa.x + acc.x * inv;
    o.y = pa.y + acc.y * inv;
    o.z = pa.z + acc.z * inv;
    o.w = pa.w + acc.w * inv;
    ((float4*)h)[(size_t)gw * 32 + lane] = o;
}

extern "C" void kernel_launch(void* const* d_in, const int* in_sizes, int n_in,
                              void* d_out, int out_size) {
    const int*   trip    = (const int*)d_in[0];
    const float* ent     = (const float*)d_in[1];
    const float* rel     = (const float*)d_in[2];
    const float* W_ent   = (const float*)d_in[3];
    const float* b_ent   = (const float*)d_in[4];
    const float* W_rel   = (const float*)d_in[5];
    const float* b_rel   = (const float*)d_in[6];
    const float* W_ent2  = (const float*)d_in[7];
    const float* b_ent2  = (const float*)d_in[8];
    const float* a_w     = (const float*)d_in[9];
    const float* a_b     = (const float*)d_in[10];

    int E = in_sizes[0] / 3;
    int N = in_sizes[1] / D;
    int R = in_sizes[2] / D;
    int nblk = (N + SCB - 1) / SCB;

    cudaFuncSetAttribute(gemm_kernel, cudaFuncAttributeMaxDynamicSharedMemorySize,
                         98304);

    prep_kernel<<<D + R + 1, D>>>(W_ent, b_ent, W_rel, b_rel, W_ent2, b_ent2,
                                  rel, a_w, R, N);                       // 0
    hist_kernel<<<1024, 256>>>(trip, E);                                 // 1
    scan1_kernel<<<nblk, SCB>>>(N);                                      // 2
    gemm_kernel<<<dim3((N + 127) / 128, 2), 256, 98304>>>(ent, a_w, N);  // 3 (profiled)
    scan2_kernel<<<1, 256>>>(nblk, N);                                   // 4
    scan3_kernel<<<nblk, SCB>>>(N);                                      // 5
    scatter_b_kernel<<<1024, 256>>>(trip, a_b, E);                       // 6
    agg_kernel<<<(N * 32 + 255) / 256, 256>>>((float*)d_out, N);         // 7
}

// round 16
// speedup vs baseline: 1.6145x; 1.6145x over previous
#include <cuda_runtime.h>
#include <cuda_fp16.h>
#include <cuda_bf16.h>
#include <cstdint>
#include <cstddef>

#define D 128
#define MAXN 100000
#define MAXE 500000
#define MAXR 237
#define SCB  512
#define NBLK ((MAXN + SCB - 1) / SCB)

// ---- scratch (device globals) ----
__device__ float  g_bias[256];
__device__ float  g_pc[MAXR * D];
__device__ float  g_qc[MAXR];
__device__ __align__(16) __nv_bfloat16 g_Mh[256 * 128];  // fused weights [col][k] hi
__device__ __align__(16) __nv_bfloat16 g_Ml[256 * 128];  // lo
__device__ float  g_pa[(size_t)MAXN * D];    // fp32
__device__ __half g_pbh[(size_t)MAXN * D];   // fp16 (gathered side)
__device__ float  g_qa[MAXN];
__device__ float  g_qb[MAXN];
__device__ float2 g_epk[MAXE];               // (b_e, dst|rel<<17)
__device__ int    g_cnt[MAXN];
__device__ int    g_rowptr[MAXN + 1];
__device__ int    g_cursor[MAXN];
__device__ int    g_bsum[NBLK];
__device__ int    g_boff[NBLK];

// ---- helpers ----
__device__ __forceinline__ uint32_t smem_u32(const void* p) {
    uint32_t a;
    asm("{ .reg .u64 t; cvta.to.shared.u64 t, %1; cvt.u32.u64 %0, t; }"
        : "=r"(a) : "l"(p));
    return a;
}
__device__ __forceinline__ uint32_t pkbf(float a, float b) {
    unsigned short x = __bfloat16_as_ushort(__float2bfloat16(a));
    unsigned short y = __bfloat16_as_ushort(__float2bfloat16(b));
    return ((uint32_t)y << 16) | x;
}
__device__ __forceinline__ void ldsm4(uint32_t& r0, uint32_t& r1, uint32_t& r2,
                                      uint32_t& r3, uint32_t addr) {
    asm volatile("ldmatrix.sync.aligned.m8n8.x4.shared.b16 {%0,%1,%2,%3}, [%4];"
                 : "=r"(r0), "=r"(r1), "=r"(r2), "=r"(r3) : "r"(addr));
}
__device__ __forceinline__ void mma16816(float* c, uint32_t a0, uint32_t a1,
                                         uint32_t a2, uint32_t a3,
                                         uint32_t b0, uint32_t b1) {
    asm volatile(
        "mma.sync.aligned.m16n8k16.row.col.f32.bf16.bf16.f32 "
        "{%0,%1,%2,%3}, {%4,%5,%6,%7}, {%8,%9}, {%0,%1,%2,%3};"
        : "+f"(c[0]), "+f"(c[1]), "+f"(c[2]), "+f"(c[3])
        : "r"(a0), "r"(a1), "r"(a2), "r"(a3), "r"(b0), "r"(b1));
}

// ---- kernel 1: weight fusion (bf16 hi/lo, [col][k]), pc, qc, bias ----
__global__ void prep_kernel(const float* __restrict__ W_ent,
                            const float* __restrict__ b_ent,
                            const float* __restrict__ W_rel,
                            const float* __restrict__ b_rel,
                            const float* __restrict__ W_ent2,
                            const float* __restrict__ b_ent2,
                            const float* __restrict__ rel_embed,
                            const float* __restrict__ a_w,
                            int n_rels, int n_nodes) {
    int b = blockIdx.x, t = threadIdx.x;
    if (b < D) {
        __shared__ float wrow[D];
        wrow[t] = W_ent[b * D + t];
        __syncthreads();
        float s0 = 0.f, s1 = 0.f;
#pragma unroll 4
        for (int k = 0; k < D; k++) {
            float w = wrow[k];
            s0 += w * W_ent2[k * D + t];
            s1 += w * W_ent2[(D + k) * D + t];
        }
        __nv_bfloat16 h0 = __float2bfloat16(s0);
        __nv_bfloat16 h1 = __float2bfloat16(s1);
        g_Mh[t * 128 + b]         = h0;
        g_Mh[(128 + t) * 128 + b] = h1;
        g_Ml[t * 128 + b]         = __float2bfloat16(s0 - __bfloat162float(h0));
        g_Ml[(128 + t) * 128 + b] = __float2bfloat16(s1 - __bfloat162float(h1));
    } else if (b < D + n_rels) {
        int r = b - D;
        __shared__ float rp[D];
        __shared__ float red[D];
        float s = b_rel[t];
#pragma unroll 4
        for (int i = 0; i < D; i++) s += rel_embed[r * D + i] * W_rel[i * D + t];
        rp[t] = s;
        __syncthreads();
        float o = b_ent2[t];
#pragma unroll 4
        for (int k = 0; k < D; k++) o += rp[k] * W_ent2[(2 * D + k) * D + t];
        g_pc[r * D + t] = o;
        red[t] = o * a_w[t];
        __syncthreads();
        for (int off = 64; off > 0; off >>= 1) {
            if (t < off) red[t] += red[t + off];
            __syncthreads();
        }
        if (t == 0) g_qc[r] = red[0];
    } else {
        float s0 = 0.f, s1 = 0.f;
        for (int k = 0; k < D; k++) {
            float bv = b_ent[k];
            s0 += bv * W_ent2[k * D + t];
            s1 += bv * W_ent2[(D + k) * D + t];
        }
        g_bias[t]     = s0;
        g_bias[D + t] = s1;
    }
    for (int i = b * blockDim.x + t; i < n_nodes; i += gridDim.x * blockDim.x)
        g_cnt[i] = 0;
}

// ---- kernel 2: out-degree histogram ----
__global__ void hist_kernel(const int* __restrict__ trip, int E) {
    for (int e = blockIdx.x * blockDim.x + threadIdx.x; e < E;
         e += gridDim.x * blockDim.x)
        atomicAdd(&g_cnt[trip[e * 3]], 1);
}

// ---- kernels 3a/3b/3c: multi-block exclusive scan ----
__global__ void scan1_kernel(int N) {
    __shared__ int sm[SCB];
    int t = threadIdx.x;
    int i = blockIdx.x * SCB + t;
    sm[t] = (i < N) ? g_cnt[i] : 0;
    __syncthreads();
    for (int off = SCB / 2; off > 0; off >>= 1) {
        if (t < off) sm[t] += sm[t + off];
        __syncthreads();
    }
    if (t == 0) g_bsum[blockIdx.x] = sm[0];
}
__global__ void scan2_kernel(int nblk, int N) {
    __shared__ int sm[256];
    int t = threadIdx.x;
    int v = (t < nblk) ? g_bsum[t] : 0;
    sm[t] = v;
    __syncthreads();
    for (int off = 1; off < 256; off <<= 1) {
        int u = (t >= off) ? sm[t - off] : 0;
        __syncthreads();
        sm[t] += u;
        __syncthreads();
    }
    if (t < nblk) g_boff[t] = sm[t] - v;
    if (t == 255) g_rowptr[N] = sm[255];
}
__global__ void scan3_kernel(int N) {
    __shared__ int sm[SCB];
    int t = threadIdx.x;
    int i = blockIdx.x * SCB + t;
    int v = (i < N) ? g_cnt[i] : 0;
    sm[t] = v;
    __syncthreads();
    for (int off = 1; off < SCB; off <<= 1) {
        int u = (t >= off) ? sm[t - off] : 0;
        __syncthreads();
        sm[t] += u;
        __syncthreads();
    }
    if (i < N) {
        int val = g_boff[blockIdx.x] + sm[t] - v;
        g_rowptr[i] = val;
        g_cursor[i] = val;
    }
}

// ---- kernel 4 (slot 3): HMMA GEMM via mma.sync bf16 hi/lo split ----
// CTA: 128 rows x 128 cols (y selects pa/pb half). Warp w: rows [16w,16w+16).
// Smem tiles stride 144B (72 bf16): 16B-aligned, ldmatrix conflict-free.
#define AST 144
__global__ __launch_bounds__(256, 2) void gemm_kernel(const float* __restrict__ ent,
                                                      const float* __restrict__ a_w,
                                                      int N) {
    extern __shared__ char smem[];
    const int AH = 0, AL = 18432, BH = 36864, BL = 55296;
    __shared__ float bias_s[128], aw_s[128];
    const int tid = threadIdx.x;
    const int wid = tid >> 5, lane = tid & 31;
    const int rb = blockIdx.x * 128;
    const int y = blockIdx.y;
    const uint32_t sb = smem_u32(smem);

    if (tid < 128) {
        bias_s[tid] = g_bias[y * 128 + tid];
        aw_s[tid] = a_w[tid];
    }

    const float4* E4 = (const float4*)ent;
    const uint2* MH2 = (const uint2*)g_Mh;
    const uint2* ML2 = (const uint2*)g_Ml;

    float acc[16][4];
    const int gid = lane >> 2, m = lane & 3;
    // ldmatrix lane address components
    const int arow_off = (wid * 16 + (lane & 15)) * AST;
    const int akb = (lane >> 4) << 3;                 // 0 or 8
    const int bn = (lane & 7) | ((lane & 16) >> 1);   // n row within n16
    const int bk = lane & 8;                          // k sub-block

#pragma unroll 1
    for (int ph = 0; ph < 2; ph++) {
        if (ph) __syncthreads();   // compute(ph-1) done before refill
        // fill A hi/lo: 128 rows x 64 k
#pragma unroll
        for (int j = 0; j < 8; j++) {
            int f = j * 256 + tid;          // 2048 float4
            int row = f >> 4, kq = f & 15;  // k = kq*4
            int grow = rb + row;
            if (grow >= N) grow = N - 1;
            float4 v = E4[(size_t)grow * 32 + ph * 16 + kq];
            __nv_bfloat16 hx = __float2bfloat16(v.x), hy = __float2bfloat16(v.y);
            __nv_bfloat16 hz = __float2bfloat16(v.z), hw = __float2bfloat16(v.w);
            uint2 uh, ul;
            uh.x = ((uint32_t)__bfloat16_as_ushort(hy) << 16) | __bfloat16_as_ushort(hx);
            uh.y = ((uint32_t)__bfloat16_as_ushort(hw) << 16) | __bfloat16_as_ushort(hz);
            ul.x = pkbf(v.x - __bfloat162float(hx), v.y - __bfloat162float(hy));
            ul.y = pkbf(v.z - __bfloat162float(hz), v.w - __bfloat162float(hw));
            *(uint2*)(smem + AH + row * AST + kq * 8) = uh;
            *(uint2*)(smem + AL + row * AST + kq * 8) = ul;
        }
        // fill B hi/lo: 128 cols x 64 k (copy pre-split weights)
#pragma unroll
        for (int j = 0; j < 8; j++) {
            int f = j * 256 + tid;          // 2048 uint2
            int col = f >> 4, kq = f & 15;
            int src = (y * 128 + col) * 32 + ph * 16 + kq;  // uint2 units
            *(uint2*)(smem + BH + col * AST + kq * 8) = MH2[src];
            *(uint2*)(smem + BL + col * AST + kq * 8) = ML2[src];
        }
        __syncthreads();

        if (ph == 0) {
#pragma unroll
            for (int nt = 0; nt < 16; nt++) {
                int col = nt * 8 + 2 * m;
                acc[nt][0] = bias_s[col];
                acc[nt][1] = bias_s[col + 1];
                acc[nt][2] = acc[nt][0];
                acc[nt][3] = acc[nt][1];
            }
        }

#pragma unroll
        for (int k16 = 0; k16 < 4; k16++) {
            int kb = k16 * 16;
            uint32_t ah0, ah1, ah2, ah3, al0, al1, al2, al3;
            ldsm4(ah0, ah1, ah2, ah3, sb + AH + arow_off + (kb + akb) * 2);
            ldsm4(al0, al1, al2, al3, sb + AL + arow_off + (kb + akb) * 2);
#pragma unroll
            for (int nt2 = 0; nt2 < 8; nt2++) {
                uint32_t boff = (nt2 * 16 + bn) * AST + (kb + bk) * 2;
                uint32_t bh0, bh1, bh2, bh3, bl0, bl1, bl2, bl3;
                ldsm4(bh0, bh1, bh2, bh3, sb + BH + boff);
                ldsm4(bl0, bl1, bl2, bl3, sb + BL + boff);
                mma16816(acc[nt2 * 2],     ah0, ah1, ah2, ah3, bh0, bh1);
                mma16816(acc[nt2 * 2],     al0, al1, al2, al3, bh0, bh1);
                mma16816(acc[nt2 * 2],     ah0, ah1, ah2, ah3, bl0, bl1);
                mma16816(acc[nt2 * 2 + 1], ah0, ah1, ah2, ah3, bh2, bh3);
                mma16816(acc[nt2 * 2 + 1], al0, al1, al2, al3, bh2, bh3);
                mma16816(acc[nt2 * 2 + 1], ah0, ah1, ah2, ah3, bl2, bl3);
            }
        }
    }

    // epilogue: rows r0 = rb+16w+gid, r1 = r0+8; cols nt*8+2m,+1
    int r0 = rb + wid * 16 + gid, r1 = r0 + 8;
    float q0 = 0.f, q1 = 0.f;
#pragma unroll
    for (int nt = 0; nt < 16; nt++) {
        int col = nt * 8 + 2 * m;
        float w0 = aw_s[col], w1 = aw_s[col + 1];
        q0 += acc[nt][0] * w0 + acc[nt][1] * w1;
        q1 += acc[nt][2] * w0 + acc[nt][3] * w1;
        if (y == 0) {
            float2 v0 = {acc[nt][0], acc[nt][1]};
            float2 v1 = {acc[nt][2], acc[nt][3]};
            if (r0 < N) *(float2*)&g_pa[(size_t)r0 * 128 + col] = v0;
            if (r1 < N) *(float2*)&g_pa[(size_t)r1 * 128 + col] = v1;
        } else {
            __half2 h0 = __floats2half2_rn(acc[nt][0], acc[nt][1]);
            __half2 h1 = __floats2half2_rn(acc[nt][2], acc[nt][3]);
            if (r0 < N) *(__half2*)&g_pbh[(size_t)r0 * 128 + col] = h0;
            if (r1 < N) *(__half2*)&g_pbh[(size_t)r1 * 128 + col] = h1;
        }
    }
    q0 += __shfl_xor_sync(0xffffffffu, q0, 1);
    q0 += __shfl_xor_sync(0xffffffffu, q0, 2);
    q1 += __shfl_xor_sync(0xffffffffu, q1, 1);
    q1 += __shfl_xor_sync(0xffffffffu, q1, 2);
    if (m == 0) {
        float* q = (y == 0) ? g_qa : g_qb;
        if (r0 < N) q[r0] = q0;
        if (r1 < N) q[r1] = q1;
    }
}

// ---- kernel 5: scatter edges into CSR + edge weight (packed record) ----
__global__ void scatter_b_kernel(const int* __restrict__ trip,
                                 const float* __restrict__ abp, int E) {
    float ab = abp[0];
    for (int e = blockIdx.x * blockDim.x + threadIdx.x; e < E;
         e += gridDim.x * blockDim.x) {
        int src = trip[e * 3];
        int dst = trip[e * 3 + 1];
        int rel = trip[e * 3 + 2];
        int p = atomicAdd(&g_cursor[src], 1);
        float s = g_qa[src] + g_qb[dst] + g_qc[rel] + ab;
        s = s > 0.f ? s : 0.01f * s;   // leaky_relu(0.01)
        float2 rec;
        rec.x = __expf(s);
        rec.y = __int_as_float(dst | (rel << 17));
        g_epk[p] = rec;
    }
}

// ---- kernel 6: warp-per-node aggregation (unrolled x2) ----
__global__ void agg_kernel(float* __restrict__ h, int N) {
    int gw = (blockIdx.x * blockDim.x + threadIdx.x) >> 5;
    int lane = threadIdx.x & 31;
    if (gw >= N) return;
    int beg = g_rowptr[gw], end = g_rowptr[gw + 1];
    if (beg == end) {
        float4 z = {0.f, 0.f, 0.f, 0.f};
        ((float4*)h)[(size_t)gw * 32 + lane] = z;
        return;
    }
    const uint2* pbh2 = (const uint2*)g_pbh;
    const float4* pc4 = (const float4*)g_pc;
    float4 acc = {0.f, 0.f, 0.f, 0.f};
    float bsum = 0.f;
    int e = beg;
    for (; e + 1 < end; e += 2) {
        float2 r0 = g_epk[e];
        float2 r1 = g_epk[e + 1];
        int p0 = __float_as_int(r0.y), p1 = __float_as_int(r1.y);
        uint2 u0 = pbh2[(size_t)(p0 & 0x1FFFF) * 32 + lane];
        uint2 u1 = pbh2[(size_t)(p1 & 0x1FFFF) * 32 + lane];
        float4 c0 = pc4[(p0 >> 17) * 32 + lane];
        float4 c1 = pc4[(p1 >> 17) * 32 + lane];
        float b0 = r0.x, b1 = r1.x;
        float2 f00 = __half22float2(*(__half2*)&u0.x);
        float2 f01 = __half22float2(*(__half2*)&u0.y);
        float2 f10 = __half22float2(*(__half2*)&u1.x);
        float2 f11 = __half22float2(*(__half2*)&u1.y);
        bsum += b0 + b1;
        acc.x += b0 * (f00.x + c0.x) + b1 * (f10.x + c1.x);
        acc.y += b0 * (f00.y + c0.y) + b1 * (f10.y + c1.y);
        acc.z += b0 * (f01.x + c0.z) + b1 * (f11.x + c1.z);
        acc.w += b0 * (f01.y + c0.w) + b1 * (f11.y + c1.w);
    }
    if (e < end) {
        float2 r0 = g_epk[e];
        int p0 = __float_as_int(r0.y);
        uint2 u0 = pbh2[(size_t)(p0 & 0x1FFFF) * 32 + lane];
        float4 c0 = pc4[(p0 >> 17) * 32 + lane];
        float b0 = r0.x;
        float2 f00 = __half22float2(*(__half2*)&u0.x);
        float2 f01 = __half22float2(*(__half2*)&u0.y);
        bsum += b0;
        acc.x += b0 * (f00.x + c0.x);
        acc.y += b0 * (f00.y + c0.y);
        acc.z += b0 * (f01.x + c0.z);
        acc.w += b0 * (f01.y + c0.w);
    }
    float4 pa = ((const float4*)g_pa)[(size_t)gw * 32 + lane];
    float inv = 1.f / bsum;
    float4 o;
    o.x = pa.x + acc.x * inv;
    o.y = pa.y + acc.y * inv;
    o.z = pa.z + acc.z * inv;
    o.w = pa.w + acc.w * inv;
    ((float4*)h)[(size_t)gw * 32 + lane] = o;
}

extern "C" void kernel_launch(void* const* d_in, const int* in_sizes, int n_in,
                              void* d_out, int out_size) {
    const int*   trip    = (const int*)d_in[0];
    const float* ent     = (const float*)d_in[1];
    const float* rel     = (const float*)d_in[2];
    const float* W_ent   = (const float*)d_in[3];
    const float* b_ent   = (const float*)d_in[4];
    const float* W_rel   = (const float*)d_in[5];
    const float* b_rel   = (const float*)d_in[6];
    const float* W_ent2  = (const float*)d_in[7];
    const float* b_ent2  = (const float*)d_in[8];
    const float* a_w     = (const float*)d_in[9];
    const float* a_b     = (const float*)d_in[10];

    int E = in_sizes[0] / 3;
    int N = in_sizes[1] / D;
    int R = in_sizes[2] / D;
    int nblk = (N + SCB - 1) / SCB;

    cudaFuncSetAttribute(gemm_kernel, cudaFuncAttributeMaxDynamicSharedMemorySize,
                         73728);

    prep_kernel<<<D + R + 1, D>>>(W_ent, b_ent, W_rel, b_rel, W_ent2, b_ent2,
                                  rel, a_w, R, N);                       // 0
    hist_kernel<<<1024, 256>>>(trip, E);                                 // 1
    scan1_kernel<<<nblk, SCB>>>(N);                                      // 2
    gemm_kernel<<<dim3((N + 127) / 128, 2), 256, 73728>>>(ent, a_w, N);  // 3 (profiled)
    scan2_kernel<<<1, 256>>>(nblk, N);                                   // 4
    scan3_kernel<<<nblk, SCB>>>(N);                                      // 5
    scatter_b_kernel<<<1024, 256>>>(trip, a_b, E);                       // 6
    agg_kernel<<<(N * 32 + 255) / 256, 256>>>((float*)d_out, N);         // 7
}

// round 17
// speedup vs baseline: 1.6441x; 1.0183x over previous
#include <cuda_runtime.h>
#include <cuda_fp16.h>
#include <cuda_bf16.h>
#include <cstdint>
#include <cstddef>

#define D 128
#define MAXN 100000
#define MAXE 500000
#define MAXR 237
#define SCB  512
#define NBLK ((MAXN + SCB - 1) / SCB)

// ---- scratch (device globals) ----
__device__ float  g_bias[256];
__device__ float  g_pc[MAXR * D];
__device__ float  g_qc[MAXR];
__device__ __align__(16) __nv_bfloat16 g_Mh[256 * 128];  // fused weights [col][k] hi
__device__ __align__(16) __nv_bfloat16 g_Ml[256 * 128];  // lo
__device__ float  g_pa[(size_t)MAXN * D];    // fp32
__device__ __half g_pbh[(size_t)MAXN * D];   // fp16 (gathered side)
__device__ float  g_qa[MAXN];
__device__ float  g_qb[MAXN];
__device__ float2 g_epk[MAXE];               // (b_e, dst|rel<<17)
__device__ int    g_cnt[MAXN];
__device__ int    g_rowptr[MAXN + 1];
__device__ int    g_cursor[MAXN];
__device__ int    g_bsum[NBLK];
__device__ int    g_boff[NBLK];

// ---- helpers ----
__device__ __forceinline__ uint32_t smem_u32(const void* p) {
    uint32_t a;
    asm("{ .reg .u64 t; cvta.to.shared.u64 t, %1; cvt.u32.u64 %0, t; }"
        : "=r"(a) : "l"(p));
    return a;
}
__device__ __forceinline__ uint32_t pkbf(float a, float b) {
    unsigned short x = __bfloat16_as_ushort(__float2bfloat16(a));
    unsigned short y = __bfloat16_as_ushort(__float2bfloat16(b));
    return ((uint32_t)y << 16) | x;
}
__device__ __forceinline__ void ldsm4(uint32_t& r0, uint32_t& r1, uint32_t& r2,
                                      uint32_t& r3, uint32_t addr) {
    asm volatile("ldmatrix.sync.aligned.m8n8.x4.shared.b16 {%0,%1,%2,%3}, [%4];"
                 : "=r"(r0), "=r"(r1), "=r"(r2), "=r"(r3) : "r"(addr));
}
__device__ __forceinline__ void mma16816(float* c, uint32_t a0, uint32_t a1,
                                         uint32_t a2, uint32_t a3,
                                         uint32_t b0, uint32_t b1) {
    asm volatile(
        "mma.sync.aligned.m16n8k16.row.col.f32.bf16.bf16.f32 "
        "{%0,%1,%2,%3}, {%4,%5,%6,%7}, {%8,%9}, {%0,%1,%2,%3};"
        : "+f"(c[0]), "+f"(c[1]), "+f"(c[2]), "+f"(c[3])
        : "r"(a0), "r"(a1), "r"(a2), "r"(a3), "r"(b0), "r"(b1));
}

// ---- kernel 1: weight fusion (bf16 hi/lo, [col][k]), pc, qc, bias ----
__global__ void prep_kernel(const float* __restrict__ W_ent,
                            const float* __restrict__ b_ent,
                            const float* __restrict__ W_rel,
                            const float* __restrict__ b_rel,
                            const float* __restrict__ W_ent2,
                            const float* __restrict__ b_ent2,
                            const float* __restrict__ rel_embed,
                            const float* __restrict__ a_w,
                            int n_rels, int n_nodes) {
    int b = blockIdx.x, t = threadIdx.x;
    if (b < D) {
        __shared__ float wrow[D];
        wrow[t] = W_ent[b * D + t];
        __syncthreads();
        float s0 = 0.f, s1 = 0.f;
#pragma unroll 4
        for (int k = 0; k < D; k++) {
            float w = wrow[k];
            s0 += w * W_ent2[k * D + t];
            s1 += w * W_ent2[(D + k) * D + t];
        }
        __nv_bfloat16 h0 = __float2bfloat16(s0);
        __nv_bfloat16 h1 = __float2bfloat16(s1);
        g_Mh[t * 128 + b]         = h0;
        g_Mh[(128 + t) * 128 + b] = h1;
        g_Ml[t * 128 + b]         = __float2bfloat16(s0 - __bfloat162float(h0));
        g_Ml[(128 + t) * 128 + b] = __float2bfloat16(s1 - __bfloat162float(h1));
    } else if (b < D + n_rels) {
        int r = b - D;
        __shared__ float rp[D];
        __shared__ float red[D];
        float s = b_rel[t];
#pragma unroll 4
        for (int i = 0; i < D; i++) s += rel_embed[r * D + i] * W_rel[i * D + t];
        rp[t] = s;
        __syncthreads();
        float o = b_ent2[t];
#pragma unroll 4
        for (int k = 0; k < D; k++) o += rp[k] * W_ent2[(2 * D + k) * D + t];
        g_pc[r * D + t] = o;
        red[t] = o * a_w[t];
        __syncthreads();
        for (int off = 64; off > 0; off >>= 1) {
            if (t < off) red[t] += red[t + off];
            __syncthreads();
        }
        if (t == 0) g_qc[r] = red[0];
    } else {
        float s0 = 0.f, s1 = 0.f;
        for (int k = 0; k < D; k++) {
            float bv = b_ent[k];
            s0 += bv * W_ent2[k * D + t];
            s1 += bv * W_ent2[(D + k) * D + t];
        }
        g_bias[t]     = s0;
        g_bias[D + t] = s1;
    }
    for (int i = b * blockDim.x + t; i < n_nodes; i += gridDim.x * blockDim.x)
        g_cnt[i] = 0;
}

// ---- kernel 2: out-degree histogram ----
__global__ void hist_kernel(const int* __restrict__ trip, int E) {
    for (int e = blockIdx.x * blockDim.x + threadIdx.x; e < E;
         e += gridDim.x * blockDim.x)
        atomicAdd(&g_cnt[trip[e * 3]], 1);
}

// ---- kernels 3a/3b/3c: multi-block exclusive scan ----
__global__ void scan1_kernel(int N) {
    __shared__ int sm[SCB];
    int t = threadIdx.x;
    int i = blockIdx.x * SCB + t;
    sm[t] = (i < N) ? g_cnt[i] : 0;
    __syncthreads();
    for (int off = SCB / 2; off > 0; off >>= 1) {
        if (t < off) sm[t] += sm[t + off];
        __syncthreads();
    }
    if (t == 0) g_bsum[blockIdx.x] = sm[0];
}
__global__ void scan2_kernel(int nblk, int N) {
    __shared__ int sm[256];
    int t = threadIdx.x;
    int v = (t < nblk) ? g_bsum[t] : 0;
    sm[t] = v;
    __syncthreads();
    for (int off = 1; off < 256; off <<= 1) {
        int u = (t >= off) ? sm[t - off] : 0;
        __syncthreads();
        sm[t] += u;
        __syncthreads();
    }
    if (t < nblk) g_boff[t] = sm[t] - v;
    if (t == 255) g_rowptr[N] = sm[255];
}
__global__ void scan3_kernel(int N) {
    __shared__ int sm[SCB];
    int t = threadIdx.x;
    int i = blockIdx.x * SCB + t;
    int v = (i < N) ? g_cnt[i] : 0;
    sm[t] = v;
    __syncthreads();
    for (int off = 1; off < SCB; off <<= 1) {
        int u = (t >= off) ? sm[t - off] : 0;
        __syncthreads();
        sm[t] += u;
        __syncthreads();
    }
    if (i < N) {
        int val = g_boff[blockIdx.x] + sm[t] - v;
        g_rowptr[i] = val;
        g_cursor[i] = val;
    }
}

// ---- kernel 4 (slot 3): HMMA GEMM, warp tile m32 x n64 (balanced LDSM) ----
// CTA: 128 rows x 128 cols (y selects pa/pb half).
// Warp w: rows [(w&3)*32, +32), cols [(w>>2)*64, +64).
// Smem tiles stride 144B: 16B-aligned, ldmatrix conflict-free.
#define AST 144
__global__ __launch_bounds__(256, 2) void gemm_kernel(const float* __restrict__ ent,
                                                      const float* __restrict__ a_w,
                                                      int N) {
    extern __shared__ char smem[];
    const int AH = 0, AL = 18432, BH = 36864, BL = 55296;
    __shared__ float bias_s[128], aw_s[128];
    const int tid = threadIdx.x;
    const int wid = tid >> 5, lane = tid & 31;
    const int rb = blockIdx.x * 128;
    const int y = blockIdx.y;
    const uint32_t sb = smem_u32(smem);
    const int mrow = (wid & 3) * 32;       // warp row base
    const int ncol = (wid >> 2) * 64;      // warp col base

    if (tid < 128) {
        bias_s[tid] = g_bias[y * 128 + tid];
        aw_s[tid] = a_w[tid];
    }

    const float4* E4 = (const float4*)ent;
    const uint2* MH2 = (const uint2*)g_Mh;
    const uint2* ML2 = (const uint2*)g_Ml;

    // acc[mt*8 + nt2][4]: mt in {0,1} (m16 tiles), nt2 in 0..7 (n8 tiles)
    float acc[16][4];
    const int gid = lane >> 2, m = lane & 3;
    // ldmatrix lane address components
    const int arow0 = (mrow + (lane & 15)) * AST;        // mt=0
    const int arow1 = (mrow + 16 + (lane & 15)) * AST;   // mt=1
    const int akb = (lane >> 4) << 3;                 // 0 or 8
    const int bn = (lane & 7) | ((lane & 16) >> 1);   // n row within n16
    const int bk = lane & 8;                          // k sub-block

#pragma unroll 1
    for (int ph = 0; ph < 2; ph++) {
        if (ph) __syncthreads();   // compute(ph-1) done before refill
        // fill A hi/lo: 128 rows x 64 k
#pragma unroll
        for (int j = 0; j < 8; j++) {
            int f = j * 256 + tid;          // 2048 float4
            int row = f >> 4, kq = f & 15;  // k = kq*4
            int grow = rb + row;
            if (grow >= N) grow = N - 1;
            float4 v = E4[(size_t)grow * 32 + ph * 16 + kq];
            __nv_bfloat16 hx = __float2bfloat16(v.x), hy = __float2bfloat16(v.y);
            __nv_bfloat16 hz = __float2bfloat16(v.z), hw = __float2bfloat16(v.w);
            uint2 uh, ul;
            uh.x = ((uint32_t)__bfloat16_as_ushort(hy) << 16) | __bfloat16_as_ushort(hx);
            uh.y = ((uint32_t)__bfloat16_as_ushort(hw) << 16) | __bfloat16_as_ushort(hz);
            ul.x = pkbf(v.x - __bfloat162float(hx), v.y - __bfloat162float(hy));
            ul.y = pkbf(v.z - __bfloat162float(hz), v.w - __bfloat162float(hw));
            *(uint2*)(smem + AH + row * AST + kq * 8) = uh;
            *(uint2*)(smem + AL + row * AST + kq * 8) = ul;
        }
        // fill B hi/lo: 128 cols x 64 k (copy pre-split weights)
#pragma unroll
        for (int j = 0; j < 8; j++) {
            int f = j * 256 + tid;          // 2048 uint2
            int col = f >> 4, kq = f & 15;
            int src = (y * 128 + col) * 32 + ph * 16 + kq;  // uint2 units
            *(uint2*)(smem + BH + col * AST + kq * 8) = MH2[src];
            *(uint2*)(smem + BL + col * AST + kq * 8) = ML2[src];
        }
        __syncthreads();

        if (ph == 0) {
#pragma unroll
            for (int nt = 0; nt < 16; nt++) {
                int col = ncol + (nt & 7) * 8 + 2 * m;
                acc[nt][0] = bias_s[col];
                acc[nt][1] = bias_s[col + 1];
                acc[nt][2] = acc[nt][0];
                acc[nt][3] = acc[nt][1];
            }
        }

#pragma unroll
        for (int k16 = 0; k16 < 4; k16++) {
            int kb = k16 * 16;
            uint32_t ah[2][4], al[2][4];
            ldsm4(ah[0][0], ah[0][1], ah[0][2], ah[0][3], sb + AH + arow0 + (kb + akb) * 2);
            ldsm4(al[0][0], al[0][1], al[0][2], al[0][3], sb + AL + arow0 + (kb + akb) * 2);
            ldsm4(ah[1][0], ah[1][1], ah[1][2], ah[1][3], sb + AH + arow1 + (kb + akb) * 2);
            ldsm4(al[1][0], al[1][1], al[1][2], al[1][3], sb + AL + arow1 + (kb + akb) * 2);
#pragma unroll
            for (int nt16 = 0; nt16 < 4; nt16++) {
                uint32_t boff = (ncol + nt16 * 16 + bn) * AST + (kb + bk) * 2;
                uint32_t bh0, bh1, bh2, bh3, bl0, bl1, bl2, bl3;
                ldsm4(bh0, bh1, bh2, bh3, sb + BH + boff);
                ldsm4(bl0, bl1, bl2, bl3, sb + BL + boff);
#pragma unroll
                for (int mt = 0; mt < 2; mt++) {
                    float* c0 = acc[mt * 8 + nt16 * 2];
                    float* c1 = acc[mt * 8 + nt16 * 2 + 1];
                    mma16816(c0, ah[mt][0], ah[mt][1], ah[mt][2], ah[mt][3], bh0, bh1);
                    mma16816(c0, al[mt][0], al[mt][1], al[mt][2], al[mt][3], bh0, bh1);
                    mma16816(c0, ah[mt][0], ah[mt][1], ah[mt][2], ah[mt][3], bl0, bl1);
                    mma16816(c1, ah[mt][0], ah[mt][1], ah[mt][2], ah[mt][3], bh2, bh3);
                    mma16816(c1, al[mt][0], al[mt][1], al[mt][2], al[mt][3], bh2, bh3);
                    mma16816(c1, ah[mt][0], ah[mt][1], ah[mt][2], ah[mt][3], bl2, bl3);
                }
            }
        }
    }

    // epilogue: per mt: rows r0 = rb+mrow+mt*16+gid, r1 = r0+8;
    // cols ncol + nt2*8 + 2m, +1
#pragma unroll
    for (int mt = 0; mt < 2; mt++) {
        int r0 = rb + mrow + mt * 16 + gid, r1 = r0 + 8;
        float q0 = 0.f, q1 = 0.f;
#pragma unroll
        for (int nt2 = 0; nt2 < 8; nt2++) {
            float* c = acc[mt * 8 + nt2];
            int col = ncol + nt2 * 8 + 2 * m;
            float w0 = aw_s[col], w1 = aw_s[col + 1];
            q0 += c[0] * w0 + c[1] * w1;
            q1 += c[2] * w0 + c[3] * w1;
            if (y == 0) {
                float2 v0 = {c[0], c[1]};
                float2 v1 = {c[2], c[3]};
                if (r0 < N) *(float2*)&g_pa[(size_t)r0 * 128 + col] = v0;
                if (r1 < N) *(float2*)&g_pa[(size_t)r1 * 128 + col] = v1;
            } else {
                __half2 h0 = __floats2half2_rn(c[0], c[1]);
                __half2 h1 = __floats2half2_rn(c[2], c[3]);
                if (r0 < N) *(__half2*)&g_pbh[(size_t)r0 * 128 + col] = h0;
                if (r1 < N) *(__half2*)&g_pbh[(size_t)r1 * 128 + col] = h1;
            }
        }
        q0 += __shfl_xor_sync(0xffffffffu, q0, 1);
        q0 += __shfl_xor_sync(0xffffffffu, q0, 2);
        q1 += __shfl_xor_sync(0xffffffffu, q1, 1);
        q1 += __shfl_xor_sync(0xffffffffu, q1, 2);
        // partial reduction across the two n-warps via atomic-free: each n-warp
        // holds only half the columns -> must combine. Use atomicAdd-free trick:
        // warps with same m-position but different n write disjoint partials;
        // combine through smem.
        __syncthreads();
        {
            __shared__ float qred[2][128];  // [mt parity reuse][row]
            int rloc0 = mrow + mt * 16 + gid, rloc1 = rloc0 + 8;
            if (m == 0) {
                if ((wid >> 2) == 0) {
                    qred[0][rloc0] = q0;
                    qred[0][rloc1] = q1;
                }
            }
            __syncthreads();
            if (m == 0 && (wid >> 2) == 1) {
                float* q = (y == 0) ? g_qa : g_qb;
                if (r0 < N) q[r0] = qred[0][rloc0] + q0;
                if (r1 < N) q[r1] = qred[0][rloc1] + q1;
            }
            __syncthreads();
        }
    }
}

// ---- kernel 5: scatter edges into CSR + edge weight (packed record) ----
__global__ void scatter_b_kernel(const int* __restrict__ trip,
                                 const float* __restrict__ abp, int E) {
    float ab = abp[0];
    for (int e = blockIdx.x * blockDim.x + threadIdx.x; e < E;
         e += gridDim.x * blockDim.x) {
        int src = trip[e * 3];
        int dst = trip[e * 3 + 1];
        int rel = trip[e * 3 + 2];
        int p = atomicAdd(&g_cursor[src], 1);
        float s = g_qa[src] + g_qb[dst] + g_qc[rel] + ab;
        s = s > 0.f ? s : 0.01f * s;   // leaky_relu(0.01)
        float2 rec;
        rec.x = __expf(s);
        rec.y = __int_as_float(dst | (rel << 17));
        g_epk[p] = rec;
    }
}

// ---- kernel 6: warp-per-node aggregation (unrolled x2) ----
__global__ void agg_kernel(float* __restrict__ h, int N) {
    int gw = (blockIdx.x * blockDim.x + threadIdx.x) >> 5;
    int lane = threadIdx.x & 31;
    if (gw >= N) return;
    int beg = g_rowptr[gw], end = g_rowptr[gw + 1];
    if (beg == end) {
        float4 z = {0.f, 0.f, 0.f, 0.f};
        ((float4*)h)[(size_t)gw * 32 + lane] = z;
        return;
    }
    const uint2* pbh2 = (const uint2*)g_pbh;
    const float4* pc4 = (const float4*)g_pc;
    float4 acc = {0.f, 0.f, 0.f, 0.f};
    float bsum = 0.f;
    int e = beg;
    for (; e + 1 < end; e += 2) {
        float2 r0 = g_epk[e];
        float2 r1 = g_epk[e + 1];
        int p0 = __float_as_int(r0.y), p1 = __float_as_int(r1.y);
        uint2 u0 = pbh2[(size_t)(p0 & 0x1FFFF) * 32 + lane];
        uint2 u1 = pbh2[(size_t)(p1 & 0x1FFFF) * 32 + lane];
        float4 c0 = pc4[(p0 >> 17) * 32 + lane];
        float4 c1 = pc4[(p1 >> 17) * 32 + lane];
        float b0 = r0.x, b1 = r1.x;
        float2 f00 = __half22float2(*(__half2*)&u0.x);
        float2 f01 = __half22float2(*(__half2*)&u0.y);
        float2 f10 = __half22float2(*(__half2*)&u1.x);
        float2 f11 = __half22float2(*(__half2*)&u1.y);
        bsum += b0 + b1;
        acc.x += b0 * (f00.x + c0.x) + b1 * (f10.x + c1.x);
        acc.y += b0 * (f00.y + c0.y) + b1 * (f10.y + c1.y);
        acc.z += b0 * (f01.x + c0.z) + b1 * (f11.x + c1.z);
        acc.w += b0 * (f01.y + c0.w) + b1 * (f11.y + c1.w);
    }
    if (e < end) {
        float2 r0 = g_epk[e];
        int p0 = __float_as_int(r0.y);
        uint2 u0 = pbh2[(size_t)(p0 & 0x1FFFF) * 32 + lane];
        float4 c0 = pc4[(p0 >> 17) * 32 + lane];
        float b0 = r0.x;
        float2 f00 = __half22float2(*(__half2*)&u0.x);
        float2 f01 = __half22float2(*(__half2*)&u0.y);
        bsum += b0;
        acc.x += b0 * (f00.x + c0.x);
        acc.y += b0 * (f00.y + c0.y);
        acc.z += b0 * (f01.x + c0.z);
        acc.w += b0 * (f01.y + c0.w);
    }
    float4 pa = ((const float4*)g_pa)[(size_t)gw * 32 + lane];
    float inv = 1.f / bsum;
    float4 o;
    o.x = pa.x + acc.x * inv;
    o.y = pa.y + acc.y * inv;
    o.z = pa.z + acc.z * inv;
    o.w = pa.w + acc.w * inv;
    ((float4*)h)[(size_t)gw * 32 + lane] = o;
}

extern "C" void kernel_launch(void* const* d_in, const int* in_sizes, int n_in,
                              void* d_out, int out_size) {
    const int*   trip    = (const int*)d_in[0];
    const float* ent     = (const float*)d_in[1];
    const float* rel     = (const float*)d_in[2];
    const float* W_ent   = (const float*)d_in[3];
    const float* b_ent   = (const float*)d_in[4];
    const float* W_rel   = (const float*)d_in[5];
    const float* b_rel   = (const float*)d_in[6];
    const float* W_ent2  = (const float*)d_in[7];
    const float* b_ent2  = (const float*)d_in[8];
    const float* a_w     = (const float*)d_in[9];
    const float* a_b     = (const float*)d_in[10];

    int E = in_sizes[0] / 3;
    int N = in_sizes[1] / D;
    int R = in_sizes[2] / D;
    int nblk = (N + SCB - 1) / SCB;

    cudaFuncSetAttribute(gemm_kernel, cudaFuncAttributeMaxDynamicSharedMemorySize,
                         73728);

    prep_kernel<<<D + R + 1, D>>>(W_ent, b_ent, W_rel, b_rel, W_ent2, b_ent2,
                                  rel, a_w, R, N);                       // 0
    hist_kernel<<<1024, 256>>>(trip, E);                                 // 1
    scan1_kernel<<<nblk, SCB>>>(N);                                      // 2
    gemm_kernel<<<dim3((N + 127) / 128, 2), 256, 73728>>>(ent, a_w, N);  // 3 (profiled)
    scan2_kernel<<<1, 256>>>(nblk, N);                                   // 4
    scan3_kernel<<<nblk, SCB>>>(N);                                      // 5
    scatter_b_kernel<<<1024, 256>>>(trip, a_b, E);                       // 6
    agg_kernel<<<(N * 32 + 255) / 256, 256>>>((float*)d_out, N);         // 7
}